// round 4
// baseline (speedup 1.0000x reference)
#include <cuda_runtime.h>
#include <math.h>

// Problem constants
#define M1    16384     // B*T*HW rows
#define CDIM  512
#define N1    1536      // 3*C
#define NH    8
#define HD    64
#define TT    16
#define HWDIM 1024
#define NPROB 128       // NH * TT

// Scratch (allocation-free rule: __device__ globals)
__device__ float g_q[(size_t)NPROB * HWDIM * HD];   // tf32-rounded, Q pre-scaled 1/8
__device__ float g_k[(size_t)NPROB * HWDIM * HD];
__device__ float g_v[(size_t)NPROB * HWDIM * HD];
__device__ float g_att[(size_t)M1 * CDIM];          // flat (h,q,t,d) row-major (16384,512)

// ---------------------------------------------------------------------------
// helpers
// ---------------------------------------------------------------------------
__device__ __forceinline__ float to_tf32(float x) {
    unsigned r;
    asm("cvt.rna.tf32.f32 %0, %1;" : "=r"(r) : "f"(x));
    return __uint_as_float(r);
}

__device__ __forceinline__ void mma8(float c[4],
                                     float a0, float a1, float a2, float a3,
                                     float b0, float b1) {
    asm volatile(
        "mma.sync.aligned.m16n8k8.row.col.f32.tf32.tf32.f32 "
        "{%0,%1,%2,%3}, {%4,%5,%6,%7}, {%8,%9}, {%0,%1,%2,%3};\n"
        : "+f"(c[0]), "+f"(c[1]), "+f"(c[2]), "+f"(c[3])
        : "r"(__float_as_uint(a0)), "r"(__float_as_uint(a1)),
          "r"(__float_as_uint(a2)), "r"(__float_as_uint(a3)),
          "r"(__float_as_uint(b0)), "r"(__float_as_uint(b1)));
}

// Fragment-native smem layouts.
// A-frag: float4 quad (ks,tg,mq,swz(g,tg)) = {A[m][k0],A[m+8][k0],A[m][k0+4],A[m+8][k0+4]}
//   read: LDS.128 at quad = ((ks*4+tg)*Mdiv16 + mq)*8 + ((g + 2*tg)&7)
__device__ __forceinline__ int afrag(int m, int k, int Mdiv16) {
    return ((((k >> 3) * 4 + (k & 3)) * Mdiv16 + (m >> 4)) * 8 +
            (((m & 7) + 2 * (k & 3)) & 7)) * 4 +
           ((m >> 3) & 1) + 2 * ((k >> 2) & 1);
}
// B-frag: float2 pair = {B[k0][n], B[k0+4][n]}
//   read: LDS.64 at pair = ((ks*4+tg)*Ndiv16 + (n>>4))*16 + (((n&15) + 4*tg)&15)
__device__ __forceinline__ int bfrag(int k, int n, int Ndiv16) {
    return ((((k >> 3) * 4 + (k & 3)) * Ndiv16 + (n >> 4)) * 16 +
            (((n & 15) + 4 * (k & 3)) & 15)) * 2 +
           ((k >> 2) & 1);
}

// ---------------------------------------------------------------------------
// TF32 tensor-core GEMM: C = A(MxK) @ B(KxN) + bias
// BM=BN=128, BK=32, 256 threads; warp grid 2(m)x4(n), warp tile 64x32.
// EPI==1: scatter into g_q/g_k/g_v (QKV projection), Q pre-scaled by 1/8.
// EPI==2: Cout[m*N+n] = acc + bias[n]
// ---------------------------------------------------------------------------
template <int EPI>
__global__ __launch_bounds__(256) void sgemm_tc(
    const float* __restrict__ A, const float* __restrict__ B,
    const float* __restrict__ bias, float* __restrict__ Cout,
    int M, int N, int K)
{
    __shared__ float As[4096];   // 128x32 A tile, frag layout
    __shared__ float Bs[4096];   // 32x128 B tile, frag layout

    const int tid  = threadIdx.x;
    const int warp = tid >> 5;
    const int lane = tid & 31;
    const int g    = lane >> 2;
    const int tg   = lane & 3;
    const int wm   = warp & 1;
    const int wn   = warp >> 1;
    const int m0   = blockIdx.y * 128;
    const int n0   = blockIdx.x * 128;

    float acc[4][4][4];
#pragma unroll
    for (int i = 0; i < 4; ++i)
#pragma unroll
        for (int j = 0; j < 4; ++j)
#pragma unroll
            for (int r = 0; r < 4; ++r) acc[i][j][r] = 0.0f;

    for (int k0 = 0; k0 < K; k0 += 32) {
        // A tile 128x32 -> frag layout
#pragma unroll
        for (int i = 0; i < 4; ++i) {
            int idx = i * 256 + tid;
            int ar = idx >> 3, ac = (idx & 7) << 2;
            float4 v = *(const float4*)(A + (size_t)(m0 + ar) * K + k0 + ac);
            As[afrag(ar, ac + 0, 8)] = to_tf32(v.x);
            As[afrag(ar, ac + 1, 8)] = to_tf32(v.y);
            As[afrag(ar, ac + 2, 8)] = to_tf32(v.z);
            As[afrag(ar, ac + 3, 8)] = to_tf32(v.w);
        }
        // B tile 32x128 -> frag layout
#pragma unroll
        for (int i = 0; i < 4; ++i) {
            int idx = i * 256 + tid;
            int br = idx >> 5, bc = (idx & 31) << 2;
            float4 v = *(const float4*)(B + (size_t)(k0 + br) * N + n0 + bc);
            Bs[bfrag(br, bc + 0, 8)] = to_tf32(v.x);
            Bs[bfrag(br, bc + 1, 8)] = to_tf32(v.y);
            Bs[bfrag(br, bc + 2, 8)] = to_tf32(v.z);
            Bs[bfrag(br, bc + 3, 8)] = to_tf32(v.w);
        }
        __syncthreads();

#pragma unroll
        for (int ks = 0; ks < 4; ++ks) {
            float4 av[4];
            float2 bv[4];
#pragma unroll
            for (int mt = 0; mt < 4; ++mt) {
                int quad = ((ks * 4 + tg) * 8 + (wm * 4 + mt)) * 8 + ((g + 2 * tg) & 7);
                av[mt] = *(const float4*)(As + quad * 4);
            }
#pragma unroll
            for (int nt = 0; nt < 4; ++nt) {
                int pair = ((ks * 4 + tg) * 8 + wn * 2 + (nt >> 1)) * 16 +
                           (((nt & 1) * 8 + g + 4 * tg) & 15);
                bv[nt] = *(const float2*)(Bs + pair * 2);
            }
#pragma unroll
            for (int mt = 0; mt < 4; ++mt)
#pragma unroll
                for (int nt = 0; nt < 4; ++nt)
                    mma8(acc[mt][nt], av[mt].x, av[mt].y, av[mt].z, av[mt].w,
                         bv[nt].x, bv[nt].y);
        }
        __syncthreads();
    }

    // ---- epilogue ----
    if (EPI == 1) {
#pragma unroll
        for (int mt = 0; mt < 4; ++mt) {
            int m  = m0 + wm * 64 + mt * 16 + g;
            int t  = m >> 10;
            int hw0 = m & 1023;
            int hw1 = (m + 8) & 1023;
#pragma unroll
            for (int nt = 0; nt < 4; ++nt) {
                int n   = n0 + wn * 32 + nt * 8 + 2 * tg;
                float2 bv = *(const float2*)(bias + n);
                int s   = n >> 9;
                int rem = n & 511;
                int h   = rem >> 6;
                int d   = rem & 63;
                float* dst = (s == 0) ? g_q : ((s == 1) ? g_k : g_v);
                float sc = (s == 0) ? 0.125f : 1.0f;
                size_t base = ((size_t)(h * 16 + t) * 1024) * 64 + d;
                float2 v0, v1;
                v0.x = to_tf32((acc[mt][nt][0] + bv.x) * sc);
                v0.y = to_tf32((acc[mt][nt][1] + bv.y) * sc);
                v1.x = to_tf32((acc[mt][nt][2] + bv.x) * sc);
                v1.y = to_tf32((acc[mt][nt][3] + bv.y) * sc);
                *(float2*)(dst + base + (size_t)hw0 * 64) = v0;
                *(float2*)(dst + base + (size_t)hw1 * 64) = v1;
            }
        }
    } else {
#pragma unroll
        for (int mt = 0; mt < 4; ++mt) {
            int m = m0 + wm * 64 + mt * 16 + g;
#pragma unroll
            for (int nt = 0; nt < 4; ++nt) {
                int n = n0 + wn * 32 + nt * 8 + 2 * tg;
                float2 bv = *(const float2*)(bias + n);
                float2 v0, v1;
                v0.x = acc[mt][nt][0] + bv.x;
                v0.y = acc[mt][nt][1] + bv.y;
                v1.x = acc[mt][nt][2] + bv.x;
                v1.y = acc[mt][nt][3] + bv.y;
                *(float2*)(Cout + (size_t)m * N + n)       = v0;
                *(float2*)(Cout + (size_t)(m + 8) * N + n) = v1;
            }
        }
    }
}

// ---------------------------------------------------------------------------
// Flash attention (TF32 mma), frag-layout smem. Block = (p, 128-q tile),
// 256 threads / 8 warps; warp w owns q rows [w*16, w*16+16).
// ---------------------------------------------------------------------------
__global__ __launch_bounds__(256, 2) void attn_kernel()
{
    extern __shared__ float sm[];
    float* Qs = sm;             // 8192: A-frag (M=128,K=64)
    float* Ks = Qs + 8192;      // 4096: B-frag (k=d 64, n=key 64)
    float* Vs = Ks + 4096;      // 4096: B-frag (k=key 64, n=d 64)
    float* Ps = Vs + 4096;      // 8192: A-frag (M=128,K=64)

    const int p  = blockIdx.y;
    const int q0 = blockIdx.x * 128;
    const float* Qg = g_q + (size_t)p * HWDIM * HD;
    const float* Kg = g_k + (size_t)p * HWDIM * HD;
    const float* Vg = g_v + (size_t)p * HWDIM * HD;

    const int tid  = threadIdx.x;
    const int w    = tid >> 5;
    const int lane = tid & 31;
    const int g    = lane >> 2;
    const int tg   = lane & 3;

    // Q tile 128x64 -> A-frag layout
#pragma unroll
    for (int i = 0; i < 8; ++i) {
        int idx = i * 256 + tid;
        int r = idx >> 4, c = (idx & 15) << 2;
        float4 v = *(const float4*)(Qg + (size_t)(q0 + r) * HD + c);
        Qs[afrag(r, c + 0, 8)] = v.x;
        Qs[afrag(r, c + 1, 8)] = v.y;
        Qs[afrag(r, c + 2, 8)] = v.z;
        Qs[afrag(r, c + 3, 8)] = v.w;
    }

    float O[8][4];
#pragma unroll
    for (int nt = 0; nt < 8; ++nt)
#pragma unroll
        for (int r = 0; r < 4; ++r) O[nt][r] = 0.0f;
    float mo[2] = {-1e30f, -1e30f};
    float l[2]  = {0.0f, 0.0f};

    for (int kt = 0; kt < 16; ++kt) {
        __syncthreads();
        // K,V 64x64 tiles -> B-frag layouts
#pragma unroll
        for (int i = 0; i < 4; ++i) {
            int idx = i * 256 + tid;
            int r = idx >> 4, c = (idx & 15) << 2;   // r: row in tile, c: d-offset
            size_t go = (size_t)(kt * 64 + r) * HD + c;
            float4 kv = *(const float4*)(Kg + go);
            float4 vv = *(const float4*)(Vg + go);
            // K: k=d (c..c+3), n=key (r)
            Ks[bfrag(c + 0, r, 4)] = kv.x;
            Ks[bfrag(c + 1, r, 4)] = kv.y;
            Ks[bfrag(c + 2, r, 4)] = kv.z;
            Ks[bfrag(c + 3, r, 4)] = kv.w;
            // V: k=key (r), n=d (c..c+3)
            Vs[bfrag(r, c + 0, 4)] = vv.x;
            Vs[bfrag(r, c + 1, 4)] = vv.y;
            Vs[bfrag(r, c + 2, 4)] = vv.z;
            Vs[bfrag(r, c + 3, 4)] = vv.w;
        }
        __syncthreads();

        // ---- S = Q K^T (Q pre-scaled by 1/8) ----
        float S[8][4];
#pragma unroll
        for (int nk = 0; nk < 8; ++nk)
#pragma unroll
            for (int r = 0; r < 4; ++r) S[nk][r] = 0.0f;

#pragma unroll
        for (int ks = 0; ks < 8; ++ks) {
            int quad = ((ks * 4 + tg) * 8 + w) * 8 + ((g + 2 * tg) & 7);
            float4 aq = *(const float4*)(Qs + quad * 4);
#pragma unroll
            for (int nk = 0; nk < 8; ++nk) {
                int pair = ((ks * 4 + tg) * 4 + (nk >> 1)) * 16 +
                           (((nk & 1) * 8 + g + 4 * tg) & 15);
                float2 bk = *(const float2*)(Ks + pair * 2);
                mma8(S[nk], aq.x, aq.y, aq.z, aq.w, bk.x, bk.y);
            }
        }

        // ---- online softmax (rows g, g+8 of this warp's 16) ----
        float mn[2] = {-1e30f, -1e30f};
#pragma unroll
        for (int nk = 0; nk < 8; ++nk) {
            mn[0] = fmaxf(mn[0], fmaxf(S[nk][0], S[nk][1]));
            mn[1] = fmaxf(mn[1], fmaxf(S[nk][2], S[nk][3]));
        }
#pragma unroll
        for (int s = 0; s < 2; ++s) {
            mn[s] = fmaxf(mn[s], __shfl_xor_sync(0xFFFFFFFFu, mn[s], 1));
            mn[s] = fmaxf(mn[s], __shfl_xor_sync(0xFFFFFFFFu, mn[s], 2));
            mn[s] = fmaxf(mn[s], mo[s]);
        }
        float al[2];
        al[0] = __expf(mo[0] - mn[0]);
        al[1] = __expf(mo[1] - mn[1]);
#pragma unroll
        for (int nt = 0; nt < 8; ++nt) {
            O[nt][0] *= al[0]; O[nt][1] *= al[0];
            O[nt][2] *= al[1]; O[nt][3] *= al[1];
        }
        float rs[2] = {0.0f, 0.0f};
        const int m = w * 16 + g;
        __syncwarp();
#pragma unroll
        for (int nk = 0; nk < 8; ++nk) {
            int c0 = nk * 8 + 2 * tg;
            float p0 = __expf(S[nk][0] - mn[0]);
            float p1 = __expf(S[nk][1] - mn[0]);
            float p2 = __expf(S[nk][2] - mn[1]);
            float p3 = __expf(S[nk][3] - mn[1]);
            rs[0] += p0 + p1;
            rs[1] += p2 + p3;
            Ps[afrag(m,     c0,     8)] = to_tf32(p0);
            Ps[afrag(m,     c0 + 1, 8)] = to_tf32(p1);
            Ps[afrag(m + 8, c0,     8)] = to_tf32(p2);
            Ps[afrag(m + 8, c0 + 1, 8)] = to_tf32(p3);
        }
        __syncwarp();
#pragma unroll
        for (int s = 0; s < 2; ++s) {
            rs[s] += __shfl_xor_sync(0xFFFFFFFFu, rs[s], 1);
            rs[s] += __shfl_xor_sync(0xFFFFFFFFu, rs[s], 2);
            l[s] = l[s] * al[s] + rs[s];
            mo[s] = mn[s];
        }

        // ---- O += P V ----
#pragma unroll
        for (int ks = 0; ks < 8; ++ks) {
            int quad = ((ks * 4 + tg) * 8 + w) * 8 + ((g + 2 * tg) & 7);
            float4 ap = *(const float4*)(Ps + quad * 4);
#pragma unroll
            for (int nt = 0; nt < 8; ++nt) {
                int pair = ((ks * 4 + tg) * 4 + (nt >> 1)) * 16 +
                           (((nt & 1) * 8 + g + 4 * tg) & 15);
                float2 bv = *(const float2*)(Vs + pair * 2);
                mma8(O[nt], ap.x, ap.y, ap.z, ap.w, bv.x, bv.y);
            }
        }
    }

    // ---- epilogue: normalize + permuted store ----
    const int h = p >> 4;
    const int t = p & 15;
    {
        int row = w * 16 + g;
        int q   = q0 + row;
        float inv0 = 1.0f / l[0];
        float inv1 = 1.0f / l[1];
        size_t base0 = ((size_t)(h * 1024 + q) * 16 + t) * 64;
        size_t base1 = ((size_t)(h * 1024 + q + 8) * 16 + t) * 64;
#pragma unroll
        for (int nt = 0; nt < 8; ++nt) {
            int d = nt * 8 + 2 * tg;
            float2 v0, v1;
            v0.x = O[nt][0] * inv0; v0.y = O[nt][1] * inv0;
            v1.x = O[nt][2] * inv1; v1.y = O[nt][3] * inv1;
            *(float2*)(g_att + base0 + d) = v0;
            *(float2*)(g_att + base1 + d) = v1;
        }
    }
}

// ---------------------------------------------------------------------------
extern "C" void kernel_launch(void* const* d_in, const int* in_sizes, int n_in,
                              void* d_out, int out_size)
{
    const float* x    = (const float*)d_in[0];
    const float* Wqkv = (const float*)d_in[1];
    const float* bqkv = (const float*)d_in[2];
    const float* Wout = (const float*)d_in[3];
    const float* bout = (const float*)d_in[4];
    float* out = (float*)d_out;

    // 1) QKV projection (TF32 TC) + scatter to per-(h,t) contiguous Q/K/V
    sgemm_tc<1><<<dim3(N1 / 128, M1 / 128), 256>>>(
        x, Wqkv, bqkv, nullptr, M1, N1, CDIM);

    // 2) flash attention (128 problems x 8 q-tiles of 128)
    const int attn_smem = (8192 + 4096 + 4096 + 8192) * (int)sizeof(float);
    cudaFuncSetAttribute(attn_kernel,
                         cudaFuncAttributeMaxDynamicSharedMemorySize, attn_smem);
    attn_kernel<<<dim3(HWDIM / 128, NPROB), 256, attn_smem>>>();

    // 3) output projection: g_att(16384x512) @ Wout(512x512) + bout
    float* gatt_ptr = nullptr;
    cudaGetSymbolAddress((void**)&gatt_ptr, g_att);
    sgemm_tc<2><<<dim3(CDIM / 128, M1 / 128), 256>>>(
        gatt_ptr, Wout, bout, out, M1, CDIM, CDIM);
}

// round 5
// speedup vs baseline: 1.5454x; 1.5454x over previous
#include <cuda_runtime.h>
#include <math.h>

// Problem constants
#define M1    16384     // B*T*HW rows
#define CDIM  512
#define N1    1536      // 3*C
#define NH    8
#define HD    64
#define TT    16
#define HWDIM 1024
#define NPROB 128       // NH * TT

// Scratch (allocation-free rule: __device__ globals)
__device__ float g_q[(size_t)NPROB * HWDIM * HD];   // tf32, Q pre-scaled 1/8
__device__ float g_k[(size_t)NPROB * HWDIM * HD];
__device__ float g_v[(size_t)NPROB * HWDIM * HD];
__device__ float g_att[(size_t)M1 * CDIM];          // tf32, flat (h,q,t,d) row-major
__device__ float g_xc[(size_t)M1 * CDIM];           // tf32 copy of x
__device__ float g_wqkvc[(size_t)CDIM * N1];        // tf32 copy of Wqkv
__device__ float g_woutc[(size_t)CDIM * CDIM];      // tf32 copy of Wout

// ---------------------------------------------------------------------------
// helpers
// ---------------------------------------------------------------------------
__device__ __forceinline__ float to_tf32(float x) {
    unsigned r;
    asm("cvt.rna.tf32.f32 %0, %1;" : "=r"(r) : "f"(x));
    return __uint_as_float(r);
}

__device__ __forceinline__ void mma8(float c[4],
                                     float a0, float a1, float a2, float a3,
                                     float b0, float b1) {
    asm volatile(
        "mma.sync.aligned.m16n8k8.row.col.f32.tf32.tf32.f32 "
        "{%0,%1,%2,%3}, {%4,%5,%6,%7}, {%8,%9}, {%0,%1,%2,%3};\n"
        : "+f"(c[0]), "+f"(c[1]), "+f"(c[2]), "+f"(c[3])
        : "r"(__float_as_uint(a0)), "r"(__float_as_uint(a1)),
          "r"(__float_as_uint(a2)), "r"(__float_as_uint(a3)),
          "r"(__float_as_uint(b0)), "r"(__float_as_uint(b1)));
}

__device__ __forceinline__ unsigned smem_u32(const void* p) {
    return (unsigned)__cvta_generic_to_shared(p);
}
__device__ __forceinline__ void cp16(unsigned dst, const void* src) {
    asm volatile("cp.async.cg.shared.global [%0], [%1], 16;" :: "r"(dst), "l"(src));
}
__device__ __forceinline__ void cp_commit() {
    asm volatile("cp.async.commit_group;");
}
template <int N>
__device__ __forceinline__ void cp_wait() {
    asm volatile("cp.async.wait_group %0;" :: "n"(N));
}

// ---------------------------------------------------------------------------
// tf32 pre-convert (elementwise, float4)
// ---------------------------------------------------------------------------
__global__ void cvt_tf32_kernel(const float* __restrict__ in,
                                float* __restrict__ out, int n4)
{
    int i = blockIdx.x * blockDim.x + threadIdx.x;
    if (i < n4) {
        float4 v = ((const float4*)in)[i];
        float4 w;
        w.x = to_tf32(v.x); w.y = to_tf32(v.y);
        w.z = to_tf32(v.z); w.w = to_tf32(v.w);
        ((float4*)out)[i] = w;
    }
}

// ---------------------------------------------------------------------------
// TF32 TC GEMM, cp.async double-buffered. C = A(MxK)@B(KxN) + bias.
// Inputs already tf32-valued in gmem. BM=BN=128, BK=32, 256 thr,
// warp grid 2(m)x4(n), warp tile 64x32.
// A smem: [128][36] row-major (4m+tg banks -> conflict-free frag reads).
// B smem: [32][132].
// EPI==1: scatter into g_q/g_k/g_v (Q pre-scaled 1/8, tf32-rounded).
// EPI==2: Cout = acc + bias.
// ---------------------------------------------------------------------------
#define ASTR 36
#define BSTR 132
#define ATILE (128 * ASTR)
#define BTILE (32 * BSTR)

__device__ __forceinline__ void gemm_issue(
    const float* __restrict__ A, const float* __restrict__ B,
    float* As, float* Bs, int tid, int kt, int buf,
    size_t m0K, int n0, int K, int N)
{
    const float* Ab = A + m0K + (size_t)kt * 32;
    float* Ad = As + buf * ATILE;
#pragma unroll
    for (int i = 0; i < 4; ++i) {
        int idx = i * 256 + tid;
        int r = idx >> 3, c4 = (idx & 7) << 2;
        cp16(smem_u32(Ad + r * ASTR + c4), Ab + (size_t)r * K + c4);
    }
    const float* Bb = B + (size_t)(kt * 32) * N + n0;
    float* Bd = Bs + buf * BTILE;
#pragma unroll
    for (int i = 0; i < 4; ++i) {
        int idx = i * 256 + tid;
        int r = idx >> 5, c4 = (idx & 31) << 2;
        cp16(smem_u32(Bd + r * BSTR + c4), Bb + (size_t)r * N + c4);
    }
    cp_commit();
}

template <int EPI>
__global__ __launch_bounds__(256) void sgemm_tc(
    const float* __restrict__ A, const float* __restrict__ B,
    const float* __restrict__ bias, float* __restrict__ Cout,
    int M, int N, int K)
{
    extern __shared__ float sh[];
    float* As = sh;                 // [2][128*36]
    float* Bs = sh + 2 * ATILE;     // [2][32*132]

    const int tid  = threadIdx.x;
    const int warp = tid >> 5;
    const int lane = tid & 31;
    const int g    = lane >> 2;
    const int tg   = lane & 3;
    const int wm   = warp & 1;
    const int wn   = warp >> 1;
    const int m0   = blockIdx.y * 128;
    const int n0   = blockIdx.x * 128;
    const size_t m0K = (size_t)m0 * K;

    float acc[4][4][4];
#pragma unroll
    for (int i = 0; i < 4; ++i)
#pragma unroll
        for (int j = 0; j < 4; ++j)
#pragma unroll
            for (int r = 0; r < 4; ++r) acc[i][j][r] = 0.0f;

    const int NT = K >> 5;
    gemm_issue(A, B, As, Bs, tid, 0, 0, m0K, n0, K, N);

    for (int kt = 0; kt < NT; ++kt) {
        if (kt + 1 < NT) {
            gemm_issue(A, B, As, Bs, tid, kt + 1, (kt + 1) & 1, m0K, n0, K, N);
            cp_wait<1>();
        } else {
            cp_wait<0>();
        }
        __syncthreads();

        const float* Ab = As + (kt & 1) * ATILE;
        const float* Bb = Bs + (kt & 1) * BTILE;
#pragma unroll
        for (int ks = 0; ks < 4; ++ks) {
            int kk = ks * 8;
            float a[4][4], b[4][2];
#pragma unroll
            for (int mt = 0; mt < 4; ++mt) {
                int m = wm * 64 + mt * 16 + g;
                a[mt][0] = Ab[m * ASTR + kk + tg];
                a[mt][1] = Ab[(m + 8) * ASTR + kk + tg];
                a[mt][2] = Ab[m * ASTR + kk + tg + 4];
                a[mt][3] = Ab[(m + 8) * ASTR + kk + tg + 4];
            }
#pragma unroll
            for (int nt = 0; nt < 4; ++nt) {
                int n = wn * 32 + nt * 8 + g;
                b[nt][0] = Bb[(kk + tg) * BSTR + n];
                b[nt][1] = Bb[(kk + tg + 4) * BSTR + n];
            }
#pragma unroll
            for (int mt = 0; mt < 4; ++mt)
#pragma unroll
                for (int nt = 0; nt < 4; ++nt)
                    mma8(acc[mt][nt], a[mt][0], a[mt][1], a[mt][2], a[mt][3],
                         b[nt][0], b[nt][1]);
        }
        __syncthreads();
    }

    // ---- epilogue ----
    if (EPI == 1) {
#pragma unroll
        for (int mt = 0; mt < 4; ++mt) {
            int m  = m0 + wm * 64 + mt * 16 + g;
            int t  = m >> 10;
            int hw0 = m & 1023;
            int hw1 = (m + 8) & 1023;
#pragma unroll
            for (int nt = 0; nt < 4; ++nt) {
                int n   = n0 + wn * 32 + nt * 8 + 2 * tg;
                float2 bv = *(const float2*)(bias + n);
                int s   = n >> 9;
                int rem = n & 511;
                int h   = rem >> 6;
                int d   = rem & 63;
                float* dst = (s == 0) ? g_q : ((s == 1) ? g_k : g_v);
                float sc = (s == 0) ? 0.125f : 1.0f;
                size_t base = ((size_t)(h * 16 + t) * 1024) * 64 + d;
                float2 v0, v1;
                v0.x = to_tf32((acc[mt][nt][0] + bv.x) * sc);
                v0.y = to_tf32((acc[mt][nt][1] + bv.y) * sc);
                v1.x = to_tf32((acc[mt][nt][2] + bv.x) * sc);
                v1.y = to_tf32((acc[mt][nt][3] + bv.y) * sc);
                *(float2*)(dst + base + (size_t)hw0 * 64) = v0;
                *(float2*)(dst + base + (size_t)hw1 * 64) = v1;
            }
        }
    } else {
#pragma unroll
        for (int mt = 0; mt < 4; ++mt) {
            int m = m0 + wm * 64 + mt * 16 + g;
#pragma unroll
            for (int nt = 0; nt < 4; ++nt) {
                int n = n0 + wn * 32 + nt * 8 + 2 * tg;
                float2 bv = *(const float2*)(bias + n);
                float2 v0, v1;
                v0.x = acc[mt][nt][0] + bv.x;
                v0.y = acc[mt][nt][1] + bv.y;
                v1.x = acc[mt][nt][2] + bv.x;
                v1.y = acc[mt][nt][3] + bv.y;
                *(float2*)(Cout + (size_t)m * N + n)       = v0;
                *(float2*)(Cout + (size_t)(m + 8) * N + n) = v1;
            }
        }
    }
}

// ---------------------------------------------------------------------------
// Flash attention (TF32 mma), cp.async double-buffered K/V, Q in registers.
// Block = (p, 128-q tile), 256 threads / 8 warps; warp w owns rows
// [w*16, w*16+16). K/V iterated in 64-key tiles with online softmax.
// ---------------------------------------------------------------------------
#define KVSTR 68
#define KVTILE (64 * KVSTR)

__device__ __forceinline__ void attn_issue(
    const float* __restrict__ Kg, const float* __restrict__ Vg,
    float* Ks, float* Vs, int tid, int kt, int buf)
{
    float* Kd = Ks + buf * KVTILE;
    float* Vd = Vs + buf * KVTILE;
#pragma unroll
    for (int i = 0; i < 4; ++i) {
        int idx = i * 256 + tid;
        int r = idx >> 4, c4 = (idx & 15) << 2;
        size_t go = (size_t)(kt * 64 + r) * HD + c4;
        cp16(smem_u32(Kd + r * KVSTR + c4), Kg + go);
        cp16(smem_u32(Vd + r * KVSTR + c4), Vg + go);
    }
    cp_commit();
}

__global__ __launch_bounds__(256) void attn_kernel()
{
    extern __shared__ float sm[];
    float* Ks = sm;                   // [2][64*68]
    float* Vs = sm + 2 * KVTILE;      // [2][64*68]
    float* Ps = sm + 4 * KVTILE;      // [128*68]

    const int p  = blockIdx.y;
    const int q0 = blockIdx.x * 128;
    const float* Qg = g_q + (size_t)p * HWDIM * HD;
    const float* Kg = g_k + (size_t)p * HWDIM * HD;
    const float* Vg = g_v + (size_t)p * HWDIM * HD;

    const int tid  = threadIdx.x;
    const int w    = tid >> 5;
    const int lane = tid & 31;
    const int g    = lane >> 2;
    const int tg   = lane & 3;
    const int m    = w * 16 + g;     // local q row (and m+8)

    attn_issue(Kg, Vg, Ks, Vs, tid, 0, 0);

    // Q fragments in registers (data already tf32 + 1/8-scaled)
    float Qr[8][4];
    {
        const float* Q0 = Qg + (size_t)(q0 + m) * HD;
        const float* Q1 = Q0 + 8 * HD;
#pragma unroll
        for (int o = 0; o < 8; ++o) {
            Qr[o][0] = __ldg(Q0 + o * 8 + tg);
            Qr[o][1] = __ldg(Q1 + o * 8 + tg);
            Qr[o][2] = __ldg(Q0 + o * 8 + tg + 4);
            Qr[o][3] = __ldg(Q1 + o * 8 + tg + 4);
        }
    }

    float O[8][4];
#pragma unroll
    for (int nt = 0; nt < 8; ++nt)
#pragma unroll
        for (int r = 0; r < 4; ++r) O[nt][r] = 0.0f;
    float mo[2] = {-1e30f, -1e30f};
    float l[2]  = {0.0f, 0.0f};

    for (int kt = 0; kt < 16; ++kt) {
        if (kt + 1 < 16) {
            attn_issue(Kg, Vg, Ks, Vs, tid, kt + 1, (kt + 1) & 1);
            cp_wait<1>();
        } else {
            cp_wait<0>();
        }
        __syncthreads();
        const float* Kb = Ks + (kt & 1) * KVTILE;
        const float* Vb = Vs + (kt & 1) * KVTILE;

        // ---- S = Q K^T ----
        float S[8][4];
#pragma unroll
        for (int nk = 0; nk < 8; ++nk)
#pragma unroll
            for (int r = 0; r < 4; ++r) S[nk][r] = 0.0f;
#pragma unroll
        for (int ks = 0; ks < 8; ++ks) {
            int kk = ks * 8;
#pragma unroll
            for (int nk = 0; nk < 8; ++nk) {
                const float* kr = Kb + (nk * 8 + g) * KVSTR + kk + tg;
                mma8(S[nk], Qr[ks][0], Qr[ks][1], Qr[ks][2], Qr[ks][3],
                     kr[0], kr[4]);
            }
        }

        // ---- online softmax (rows m, m+8) ----
        float mn[2] = {-1e30f, -1e30f};
#pragma unroll
        for (int nk = 0; nk < 8; ++nk) {
            mn[0] = fmaxf(mn[0], fmaxf(S[nk][0], S[nk][1]));
            mn[1] = fmaxf(mn[1], fmaxf(S[nk][2], S[nk][3]));
        }
#pragma unroll
        for (int s = 0; s < 2; ++s) {
            mn[s] = fmaxf(mn[s], __shfl_xor_sync(0xFFFFFFFFu, mn[s], 1));
            mn[s] = fmaxf(mn[s], __shfl_xor_sync(0xFFFFFFFFu, mn[s], 2));
            mn[s] = fmaxf(mn[s], mo[s]);
        }
        float al[2];
        al[0] = __expf(mo[0] - mn[0]);
        al[1] = __expf(mo[1] - mn[1]);
#pragma unroll
        for (int nt = 0; nt < 8; ++nt) {
            O[nt][0] *= al[0]; O[nt][1] *= al[0];
            O[nt][2] *= al[1]; O[nt][3] *= al[1];
        }
        float rs[2] = {0.0f, 0.0f};
        __syncwarp();
#pragma unroll
        for (int nk = 0; nk < 8; ++nk) {
            int c0 = nk * 8 + 2 * tg;
            float p0 = __expf(S[nk][0] - mn[0]);
            float p1 = __expf(S[nk][1] - mn[0]);
            float p2 = __expf(S[nk][2] - mn[1]);
            float p3 = __expf(S[nk][3] - mn[1]);
            rs[0] += p0 + p1;
            rs[1] += p2 + p3;
            Ps[m * KVSTR + c0]           = to_tf32(p0);
            Ps[m * KVSTR + c0 + 1]       = to_tf32(p1);
            Ps[(m + 8) * KVSTR + c0]     = to_tf32(p2);
            Ps[(m + 8) * KVSTR + c0 + 1] = to_tf32(p3);
        }
        __syncwarp();
#pragma unroll
        for (int s = 0; s < 2; ++s) {
            rs[s] += __shfl_xor_sync(0xFFFFFFFFu, rs[s], 1);
            rs[s] += __shfl_xor_sync(0xFFFFFFFFu, rs[s], 2);
            l[s] = l[s] * al[s] + rs[s];
            mo[s] = mn[s];
        }

        // ---- O += P V ----
#pragma unroll
        for (int ks = 0; ks < 8; ++ks) {
            int kk = ks * 8;
            float a0 = Ps[m * KVSTR + kk + tg];
            float a1 = Ps[(m + 8) * KVSTR + kk + tg];
            float a2 = Ps[m * KVSTR + kk + tg + 4];
            float a3 = Ps[(m + 8) * KVSTR + kk + tg + 4];
#pragma unroll
            for (int nt = 0; nt < 8; ++nt) {
                const float* vr = Vb + (kk + tg) * KVSTR + nt * 8 + g;
                mma8(O[nt], a0, a1, a2, a3, vr[0], vr[4 * KVSTR]);
            }
        }
        __syncthreads();
    }

    // ---- epilogue: normalize + tf32-round + permuted store ----
    const int h = p >> 4;
    const int t = p & 15;
    {
        int q = q0 + m;
        float inv0 = 1.0f / l[0];
        float inv1 = 1.0f / l[1];
        size_t base0 = ((size_t)(h * 1024 + q) * 16 + t) * 64;
        size_t base1 = ((size_t)(h * 1024 + q + 8) * 16 + t) * 64;
#pragma unroll
        for (int nt = 0; nt < 8; ++nt) {
            int d = nt * 8 + 2 * tg;
            float2 v0, v1;
            v0.x = to_tf32(O[nt][0] * inv0); v0.y = to_tf32(O[nt][1] * inv0);
            v1.x = to_tf32(O[nt][2] * inv1); v1.y = to_tf32(O[nt][3] * inv1);
            *(float2*)(g_att + base0 + d) = v0;
            *(float2*)(g_att + base1 + d) = v1;
        }
    }
}

// ---------------------------------------------------------------------------
extern "C" void kernel_launch(void* const* d_in, const int* in_sizes, int n_in,
                              void* d_out, int out_size)
{
    const float* x    = (const float*)d_in[0];
    const float* Wqkv = (const float*)d_in[1];
    const float* bqkv = (const float*)d_in[2];
    const float* Wout = (const float*)d_in[3];
    const float* bout = (const float*)d_in[4];
    float* out = (float*)d_out;

    float *xc, *wqkvc, *woutc, *gatt_ptr;
    cudaGetSymbolAddress((void**)&xc, g_xc);
    cudaGetSymbolAddress((void**)&wqkvc, g_wqkvc);
    cudaGetSymbolAddress((void**)&woutc, g_woutc);
    cudaGetSymbolAddress((void**)&gatt_ptr, g_att);

    // 0) pre-convert inputs to tf32 (enables raw cp.async in GEMMs)
    cvt_tf32_kernel<<<(M1 * CDIM / 4 + 255) / 256, 256>>>(x, xc, M1 * CDIM / 4);
    cvt_tf32_kernel<<<(CDIM * N1 / 4 + 255) / 256, 256>>>(Wqkv, wqkvc, CDIM * N1 / 4);
    cvt_tf32_kernel<<<(CDIM * CDIM / 4 + 255) / 256, 256>>>(Wout, woutc, CDIM * CDIM / 4);

    const int gemm_smem = 2 * (ATILE + BTILE) * (int)sizeof(float);
    cudaFuncSetAttribute(sgemm_tc<1>,
                         cudaFuncAttributeMaxDynamicSharedMemorySize, gemm_smem);
    cudaFuncSetAttribute(sgemm_tc<2>,
                         cudaFuncAttributeMaxDynamicSharedMemorySize, gemm_smem);

    // 1) QKV projection + scatter
    sgemm_tc<1><<<dim3(N1 / 128, M1 / 128), 256, gemm_smem>>>(
        xc, wqkvc, bqkv, nullptr, M1, N1, CDIM);

    // 2) flash attention
    const int attn_smem = (4 * KVTILE + 128 * KVSTR) * (int)sizeof(float);
    cudaFuncSetAttribute(attn_kernel,
                         cudaFuncAttributeMaxDynamicSharedMemorySize, attn_smem);
    attn_kernel<<<dim3(HWDIM / 128, NPROB), 256, attn_smem>>>();

    // 3) output projection
    sgemm_tc<2><<<dim3(CDIM / 128, M1 / 128), 256, gemm_smem>>>(
        gatt_ptr, woutc, bout, out, M1, CDIM, CDIM);
}

// round 7
// speedup vs baseline: 1.7612x; 1.1396x over previous
#include <cuda_runtime.h>
#include <math.h>
#include <stdint.h>

// Problem constants
#define M1    16384     // B*T*HW rows
#define CDIM  512
#define N1    1536      // 3*C
#define NH    8
#define HD    64
#define TT    16
#define HWDIM 1024
#define NPROB 128       // NH * TT

// Scratch (allocation-free rule: __device__ globals)
__device__ float g_q[(size_t)NPROB * HWDIM * HD];   // [p][hw][d], tf32, pre-scaled 1/8
__device__ float g_k[(size_t)NPROB * HWDIM * HD];   // [p][key][perm(d)] col-interleaved
__device__ float g_vt[(size_t)NPROB * HD * HWDIM];  // [p][d][perm(key)] transposed+interleaved
__device__ float g_att[(size_t)M1 * CDIM];          // tf32, flat (h,q,t,d)
__device__ float g_xc[(size_t)M1 * CDIM];           // tf32 copy of x
__device__ float g_wqkvc[(size_t)CDIM * N1];        // tf32 copy of Wqkv
__device__ float g_woutc[(size_t)CDIM * CDIM];      // tf32 copy of Wout

// ---------------------------------------------------------------------------
// helpers
// ---------------------------------------------------------------------------
__device__ __forceinline__ float to_tf32(float x) {
    unsigned r;
    asm("cvt.rna.tf32.f32 %0, %1;" : "=r"(r) : "f"(x));
    return __uint_as_float(r);
}

__device__ __forceinline__ void mma8(float c[4],
                                     float a0, float a1, float a2, float a3,
                                     float b0, float b1) {
    asm volatile(
        "mma.sync.aligned.m16n8k8.row.col.f32.tf32.tf32.f32 "
        "{%0,%1,%2,%3}, {%4,%5,%6,%7}, {%8,%9}, {%0,%1,%2,%3};\n"
        : "+f"(c[0]), "+f"(c[1]), "+f"(c[2]), "+f"(c[3])
        : "r"(__float_as_uint(a0)), "r"(__float_as_uint(a1)),
          "r"(__float_as_uint(a2)), "r"(__float_as_uint(a3)),
          "r"(__float_as_uint(b0)), "r"(__float_as_uint(b1)));
}

__device__ __forceinline__ unsigned smem_u32(const void* p) {
    return (unsigned)__cvta_generic_to_shared(p);
}
__device__ __forceinline__ void cp16(unsigned dst, const void* src) {
    asm volatile("cp.async.cg.shared.global [%0], [%1], 16;" :: "r"(dst), "l"(src));
}
__device__ __forceinline__ void cp_commit() {
    asm volatile("cp.async.commit_group;");
}
template <int N>
__device__ __forceinline__ void cp_wait() {
    asm volatile("cp.async.wait_group %0;" :: "n"(N));
}

// within-8-block interleave: pairs (t, t+4) -> positions (2t, 2t+1)
__device__ __forceinline__ int perm8(int j) {
    return ((j & 3) << 1) | ((j >> 2) & 1);
}
__device__ __forceinline__ int P8(int d) {
    return (d & ~7) | perm8(d & 7);
}

// ---------------------------------------------------------------------------
// tf32 pre-convert (elementwise, float4)
// ---------------------------------------------------------------------------
__global__ void cvt_tf32_kernel(const float* __restrict__ in,
                                float* __restrict__ out, int n4)
{
    int i = blockIdx.x * blockDim.x + threadIdx.x;
    if (i < n4) {
        float4 v = ((const float4*)in)[i];
        float4 w;
        w.x = to_tf32(v.x); w.y = to_tf32(v.y);
        w.z = to_tf32(v.z); w.w = to_tf32(v.w);
        ((float4*)out)[i] = w;
    }
}

// ---------------------------------------------------------------------------
// TF32 TC GEMM (R5-proven), cp.async double-buffered. C = A(MxK)@B(KxN)+bias.
// EPI==1: QKV scatter (Q row-major pre-scaled; K col-interleaved; V transposed)
// EPI==2: Cout = acc + bias
// ---------------------------------------------------------------------------
#define ASTR 36
#define BSTR 132
#define ATILE (128 * ASTR)
#define BTILE (32 * BSTR)

__device__ __forceinline__ void gemm_issue(
    const float* __restrict__ A, const float* __restrict__ B,
    float* As, float* Bs, int tid, int kt, int buf,
    size_t m0K, int n0, int K, int N)
{
    const float* Ab = A + m0K + (size_t)kt * 32;
    float* Ad = As + buf * ATILE;
#pragma unroll
    for (int i = 0; i < 4; ++i) {
        int idx = i * 256 + tid;
        int r = idx >> 3, c4 = (idx & 7) << 2;
        cp16(smem_u32(Ad + r * ASTR + c4), Ab + (size_t)r * K + c4);
    }
    const float* Bb = B + (size_t)(kt * 32) * N + n0;
    float* Bd = Bs + buf * BTILE;
#pragma unroll
    for (int i = 0; i < 4; ++i) {
        int idx = i * 256 + tid;
        int r = idx >> 5, c4 = (idx & 31) << 2;
        cp16(smem_u32(Bd + r * BSTR + c4), Bb + (size_t)r * N + c4);
    }
    cp_commit();
}

template <int EPI>
__global__ __launch_bounds__(256) void sgemm_tc(
    const float* __restrict__ A, const float* __restrict__ B,
    const float* __restrict__ bias, float* __restrict__ Cout,
    int M, int N, int K)
{
    extern __shared__ float sh[];
    float* As = sh;
    float* Bs = sh + 2 * ATILE;

    const int tid  = threadIdx.x;
    const int warp = tid >> 5;
    const int lane = tid & 31;
    const int g    = lane >> 2;
    const int tg   = lane & 3;
    const int wm   = warp & 1;
    const int wn   = warp >> 1;
    const int m0   = blockIdx.y * 128;
    const int n0   = blockIdx.x * 128;
    const size_t m0K = (size_t)m0 * K;

    float acc[4][4][4];
#pragma unroll
    for (int i = 0; i < 4; ++i)
#pragma unroll
        for (int j = 0; j < 4; ++j)
#pragma unroll
            for (int r = 0; r < 4; ++r) acc[i][j][r] = 0.0f;

    const int NT = K >> 5;
    gemm_issue(A, B, As, Bs, tid, 0, 0, m0K, n0, K, N);

    for (int kt = 0; kt < NT; ++kt) {
        if (kt + 1 < NT) {
            gemm_issue(A, B, As, Bs, tid, kt + 1, (kt + 1) & 1, m0K, n0, K, N);
            cp_wait<1>();
        } else {
            cp_wait<0>();
        }
        __syncthreads();

        const float* Ab = As + (kt & 1) * ATILE;
        const float* Bb = Bs + (kt & 1) * BTILE;
#pragma unroll
        for (int ks = 0; ks < 4; ++ks) {
            int kk = ks * 8;
            float a[4][4], b[4][2];
#pragma unroll
            for (int mt = 0; mt < 4; ++mt) {
                int m = wm * 64 + mt * 16 + g;
                a[mt][0] = Ab[m * ASTR + kk + tg];
                a[mt][1] = Ab[(m + 8) * ASTR + kk + tg];
                a[mt][2] = Ab[m * ASTR + kk + tg + 4];
                a[mt][3] = Ab[(m + 8) * ASTR + kk + tg + 4];
            }
#pragma unroll
            for (int nt = 0; nt < 4; ++nt) {
                int n = wn * 32 + nt * 8 + g;
                b[nt][0] = Bb[(kk + tg) * BSTR + n];
                b[nt][1] = Bb[(kk + tg + 4) * BSTR + n];
            }
#pragma unroll
            for (int mt = 0; mt < 4; ++mt)
#pragma unroll
                for (int nt = 0; nt < 4; ++nt)
                    mma8(acc[mt][nt], a[mt][0], a[mt][1], a[mt][2], a[mt][3],
                         b[nt][0], b[nt][1]);
        }
        __syncthreads();
    }

    // ---- epilogue ----
    if (EPI == 1) {
#pragma unroll
        for (int mt = 0; mt < 4; ++mt) {
            int m  = m0 + wm * 64 + mt * 16 + g;
            int t  = m >> 10;
            int hw0 = m & 1023;
            int hw1 = (m + 8) & 1023;
#pragma unroll
            for (int nt = 0; nt < 4; ++nt) {
                int n   = n0 + wn * 32 + nt * 8 + 2 * tg;
                float2 bv = *(const float2*)(bias + n);
                int s   = n >> 9;
                int rem = n & 511;
                int h   = rem >> 6;
                int d   = rem & 63;          // even
                float v00 = acc[mt][nt][0] + bv.x;   // (hw0, d)
                float v01 = acc[mt][nt][1] + bv.y;   // (hw0, d+1)
                float v10 = acc[mt][nt][2] + bv.x;   // (hw1, d)
                float v11 = acc[mt][nt][3] + bv.y;   // (hw1, d+1)
                if (s == 0) {
                    size_t base = ((size_t)(h * 16 + t) * 1024) * 64 + d;
                    float2 v0, v1;
                    v0.x = to_tf32(v00 * 0.125f); v0.y = to_tf32(v01 * 0.125f);
                    v1.x = to_tf32(v10 * 0.125f); v1.y = to_tf32(v11 * 0.125f);
                    *(float2*)(g_q + base + (size_t)hw0 * 64) = v0;
                    *(float2*)(g_q + base + (size_t)hw1 * 64) = v1;
                } else if (s == 1) {
                    // K: column-interleaved within 8-blocks
                    size_t base = ((size_t)(h * 16 + t) * 1024) * 64;
                    int p0 = P8(d), p1 = P8(d + 1);
                    g_k[base + (size_t)hw0 * 64 + p0] = to_tf32(v00);
                    g_k[base + (size_t)hw0 * 64 + p1] = to_tf32(v01);
                    g_k[base + (size_t)hw1 * 64 + p0] = to_tf32(v10);
                    g_k[base + (size_t)hw1 * 64 + p1] = to_tf32(v11);
                } else {
                    // V: transposed [d][key], key interleaved within 8-blocks
                    size_t base = ((size_t)(h * 16 + t) * 64) * 1024;
                    int b0 = (hw0 & ~7) | perm8(hw0 & 7);
                    int b1 = (hw1 & ~7) | perm8(hw1 & 7);
                    g_vt[base + (size_t)d * 1024 + b0]       = to_tf32(v00);
                    g_vt[base + (size_t)(d + 1) * 1024 + b0] = to_tf32(v01);
                    g_vt[base + (size_t)d * 1024 + b1]       = to_tf32(v10);
                    g_vt[base + (size_t)(d + 1) * 1024 + b1] = to_tf32(v11);
                }
            }
        }
    } else {
#pragma unroll
        for (int mt = 0; mt < 4; ++mt) {
            int m = m0 + wm * 64 + mt * 16 + g;
#pragma unroll
            for (int nt = 0; nt < 4; ++nt) {
                int n = n0 + wn * 32 + nt * 8 + 2 * tg;
                float2 bv = *(const float2*)(bias + n);
                float2 v0, v1;
                v0.x = acc[mt][nt][0] + bv.x;
                v0.y = acc[mt][nt][1] + bv.y;
                v1.x = acc[mt][nt][2] + bv.x;
                v1.y = acc[mt][nt][3] + bv.y;
                *(float2*)(Cout + (size_t)m * N + n)       = v0;
                *(float2*)(Cout + (size_t)(m + 8) * N + n) = v1;
            }
        }
    }
}

// ---------------------------------------------------------------------------
// Flash attention (TF32 mma.sync). 256 thr / 8 warps, warp w owns q rows
// [w*16, w*16+16). K/V double-buffered cp.async; all MMA operand reads are
// LDS.64 pairs (interleaved gmem layouts); P relayout via quad shuffles.
// ---------------------------------------------------------------------------
#define KVSTR 72
#define KVTILE (64 * KVSTR)

__device__ __forceinline__ void attn_issue(
    const float* __restrict__ Kg, const float* __restrict__ Vtg,
    float* Ks, float* Vs, int tid, int kt, int buf)
{
    float* Kd = Ks + buf * KVTILE;
    float* Vd = Vs + buf * KVTILE;
#pragma unroll
    for (int i = 0; i < 4; ++i) {
        int idx = i * 256 + tid;
        int r = idx >> 4, c4 = (idx & 15) << 2;
        cp16(smem_u32(Kd + r * KVSTR + c4), Kg + (size_t)(kt * 64 + r) * 64 + c4);
        cp16(smem_u32(Vd + r * KVSTR + c4), Vtg + (size_t)r * 1024 + kt * 64 + c4);
    }
    cp_commit();
}

__global__ __launch_bounds__(256, 2) void attn_kernel()
{
    extern __shared__ float sm[];
    float* Ks = sm;                   // [2][64*72]
    float* Vs = sm + 2 * KVTILE;      // [2][64*72]

    const int p  = blockIdx.y;
    const int q0 = blockIdx.x * 128;
    const float* Qg  = g_q  + (size_t)p * HWDIM * HD;
    const float* Kg  = g_k  + (size_t)p * HWDIM * HD;
    const float* Vtg = g_vt + (size_t)p * HD * HWDIM;

    const int tid  = threadIdx.x;
    const int w    = tid >> 5;
    const int lane = tid & 31;
    const int g    = lane >> 2;
    const int tg   = lane & 3;
    const int m    = w * 16 + g;     // local q row (and m+8)
    const int src1 = (lane & ~3) + (tg >> 1);       // quad shuffle sources
    const int src2 = src1 + 2;
    const bool hi  = (tg & 1);

    attn_issue(Kg, Vtg, Ks, Vs, tid, 0, 0);

    // Q fragments in registers (tf32 + 1/8-scaled already)
    float Qr[8][4];
    {
        const float* Q0 = Qg + (size_t)(q0 + m) * HD;
        const float* Q1 = Q0 + 8 * HD;
#pragma unroll
        for (int o = 0; o < 8; ++o) {
            Qr[o][0] = __ldg(Q0 + o * 8 + tg);
            Qr[o][1] = __ldg(Q1 + o * 8 + tg);
            Qr[o][2] = __ldg(Q0 + o * 8 + tg + 4);
            Qr[o][3] = __ldg(Q1 + o * 8 + tg + 4);
        }
    }

    float O[8][4];
#pragma unroll
    for (int nt = 0; nt < 8; ++nt)
#pragma unroll
        for (int r = 0; r < 4; ++r) O[nt][r] = 0.0f;
    float mo[2] = {-1e30f, -1e30f};
    float l[2]  = {0.0f, 0.0f};

    for (int kt = 0; kt < 16; ++kt) {
        if (kt + 1 < 16) {
            attn_issue(Kg, Vtg, Ks, Vs, tid, kt + 1, (kt + 1) & 1);
            cp_wait<1>();
        } else {
            cp_wait<0>();
        }
        __syncthreads();
        const float* Kb = Ks + (kt & 1) * KVTILE;
        const float* Vb = Vs + (kt & 1) * KVTILE;

        // ---- S = Q K^T ----
        float S[8][4];
#pragma unroll
        for (int nk = 0; nk < 8; ++nk)
#pragma unroll
            for (int r = 0; r < 4; ++r) S[nk][r] = 0.0f;
#pragma unroll
        for (int ks = 0; ks < 8; ++ks) {
            int kk = ks * 8;
#pragma unroll
            for (int nk = 0; nk < 8; ++nk) {
                float2 bk = *(const float2*)(Kb + (nk * 8 + g) * KVSTR + kk + 2 * tg);
                mma8(S[nk], Qr[ks][0], Qr[ks][1], Qr[ks][2], Qr[ks][3],
                     bk.x, bk.y);
            }
        }

        // ---- online softmax (rows m, m+8) ----
        float mn[2] = {-1e30f, -1e30f};
#pragma unroll
        for (int nk = 0; nk < 8; ++nk) {
            mn[0] = fmaxf(mn[0], fmaxf(S[nk][0], S[nk][1]));
            mn[1] = fmaxf(mn[1], fmaxf(S[nk][2], S[nk][3]));
        }
#pragma unroll
        for (int s = 0; s < 2; ++s) {
            mn[s] = fmaxf(mn[s], __shfl_xor_sync(0xFFFFFFFFu, mn[s], 1));
            mn[s] = fmaxf(mn[s], __shfl_xor_sync(0xFFFFFFFFu, mn[s], 2));
            mn[s] = fmaxf(mn[s], mo[s]);
        }
        float al[2];
        al[0] = __expf(mo[0] - mn[0]);
        al[1] = __expf(mo[1] - mn[1]);
#pragma unroll
        for (int nt = 0; nt < 8; ++nt) {
            O[nt][0] *= al[0]; O[nt][1] *= al[0];
            O[nt][2] *= al[1]; O[nt][3] *= al[1];
        }
        float rs[2] = {0.0f, 0.0f};
#pragma unroll
        for (int nk = 0; nk < 8; ++nk) {
            float p0 = __expf(S[nk][0] - mn[0]);
            float p1 = __expf(S[nk][1] - mn[0]);
            float p2 = __expf(S[nk][2] - mn[1]);
            float p3 = __expf(S[nk][3] - mn[1]);
            rs[0] += p0 + p1;
            rs[1] += p2 + p3;
            S[nk][0] = to_tf32(p0);
            S[nk][1] = to_tf32(p1);
            S[nk][2] = to_tf32(p2);
            S[nk][3] = to_tf32(p3);
        }
#pragma unroll
        for (int s = 0; s < 2; ++s) {
            rs[s] += __shfl_xor_sync(0xFFFFFFFFu, rs[s], 1);
            rs[s] += __shfl_xor_sync(0xFFFFFFFFu, rs[s], 2);
            l[s] = l[s] * al[s] + rs[s];
            mo[s] = mn[s];
        }

        // ---- O += P V (P relayout C-frag -> A-frag via quad shuffles) ----
#pragma unroll
        for (int ks = 0; ks < 8; ++ks) {
            float u0 = __shfl_sync(0xFFFFFFFFu, S[ks][0], src1);
            float u1 = __shfl_sync(0xFFFFFFFFu, S[ks][1], src1);
            float u2 = __shfl_sync(0xFFFFFFFFu, S[ks][2], src1);
            float u3 = __shfl_sync(0xFFFFFFFFu, S[ks][3], src1);
            float w0 = __shfl_sync(0xFFFFFFFFu, S[ks][0], src2);
            float w1 = __shfl_sync(0xFFFFFFFFu, S[ks][1], src2);
            float w2 = __shfl_sync(0xFFFFFFFFu, S[ks][2], src2);
            float w3 = __shfl_sync(0xFFFFFFFFu, S[ks][3], src2);
            float a0 = hi ? u1 : u0;    // P[m][kk+tg]
            float a1 = hi ? u3 : u2;    // P[m+8][kk+tg]
            float a2 = hi ? w1 : w0;    // P[m][kk+tg+4]
            float a3 = hi ? w3 : w2;    // P[m+8][kk+tg+4]
            int kk = ks * 8;
#pragma unroll
            for (int nt = 0; nt < 8; ++nt) {
                float2 bv = *(const float2*)(Vb + (nt * 8 + g) * KVSTR + kk + 2 * tg);
                mma8(O[nt], a0, a1, a2, a3, bv.x, bv.y);
            }
        }
        __syncthreads();
    }

    // ---- epilogue: normalize + tf32-round + permuted store ----
    const int h = p >> 4;
    const int t = p & 15;
    {
        int q = q0 + m;
        float inv0 = 1.0f / l[0];
        float inv1 = 1.0f / l[1];
        size_t base0 = ((size_t)(h * 1024 + q) * 16 + t) * 64;
        size_t base1 = ((size_t)(h * 1024 + q + 8) * 16 + t) * 64;
#pragma unroll
        for (int nt = 0; nt < 8; ++nt) {
            int d = nt * 8 + 2 * tg;
            float2 v0, v1;
            v0.x = to_tf32(O[nt][0] * inv0); v0.y = to_tf32(O[nt][1] * inv0);
            v1.x = to_tf32(O[nt][2] * inv1); v1.y = to_tf32(O[nt][3] * inv1);
            *(float2*)(g_att + base0 + d) = v0;
            *(float2*)(g_att + base1 + d) = v1;
        }
    }
}

// ---------------------------------------------------------------------------
extern "C" void kernel_launch(void* const* d_in, const int* in_sizes, int n_in,
                              void* d_out, int out_size)
{
    const float* x    = (const float*)d_in[0];
    const float* Wqkv = (const float*)d_in[1];
    const float* bqkv = (const float*)d_in[2];
    const float* Wout = (const float*)d_in[3];
    const float* bout = (const float*)d_in[4];
    float* out = (float*)d_out;

    float *xc, *wqkvc, *woutc, *gatt_ptr;
    cudaGetSymbolAddress((void**)&xc, g_xc);
    cudaGetSymbolAddress((void**)&wqkvc, g_wqkvc);
    cudaGetSymbolAddress((void**)&woutc, g_woutc);
    cudaGetSymbolAddress((void**)&gatt_ptr, g_att);

    // 0) pre-convert inputs to tf32
    cvt_tf32_kernel<<<(M1 * CDIM / 4 + 255) / 256, 256>>>(x, xc, M1 * CDIM / 4);
    cvt_tf32_kernel<<<(CDIM * N1 / 4 + 255) / 256, 256>>>(Wqkv, wqkvc, CDIM * N1 / 4);
    cvt_tf32_kernel<<<(CDIM * CDIM / 4 + 255) / 256, 256>>>(Wout, woutc, CDIM * CDIM / 4);

    const int gemm_smem = 2 * (ATILE + BTILE) * (int)sizeof(float);
    cudaFuncSetAttribute(sgemm_tc<1>,
                         cudaFuncAttributeMaxDynamicSharedMemorySize, gemm_smem);
    cudaFuncSetAttribute(sgemm_tc<2>,
                         cudaFuncAttributeMaxDynamicSharedMemorySize, gemm_smem);

    // 1) QKV projection + scatter (Q row-major, K interleaved, V transposed)
    sgemm_tc<1><<<dim3(N1 / 128, M1 / 128), 256, gemm_smem>>>(
        xc, wqkvc, bqkv, nullptr, M1, N1, CDIM);

    // 2) flash attention
    const int attn_smem = 4 * KVTILE * (int)sizeof(float);
    cudaFuncSetAttribute(attn_kernel,
                         cudaFuncAttributeMaxDynamicSharedMemorySize, attn_smem);
    attn_kernel<<<dim3(HWDIM / 128, NPROB), 256, attn_smem>>>();

    // 3) output projection
    sgemm_tc<2><<<dim3(CDIM / 128, M1 / 128), 256, gemm_smem>>>(
        gatt_ptr, woutc, bout, out, M1, CDIM, CDIM);
}